// round 4
// baseline (speedup 1.0000x reference)
#include <cuda_runtime.h>
#include <math.h>

// Problem constants (match reference)
#define NQ   4096     // NUM_Q
#define SQ   256      // MAX_STEP
#define NB   64       // BATCH
#define ROWW (2 * NQ) // 8192 floats per batch row

// Scratch (no device allocation allowed)
__device__ int   g_code[NB * SQ];   // per (b,s): (a<<12)|q_idx, or -1 if padded row
__device__ float g_partial[NB];     // per-student loss

// ---------------------------------------------------------------------------
// Phase 1: scan batch rows s=1..255, find the one-hot position and its half.
// One block (256 threads) per row; 8 x float4 coalesced loads per thread.
// ---------------------------------------------------------------------------
__global__ __launch_bounds__(256) void scan_rows(const float* __restrict__ batch) {
    int blk = blockIdx.x;               // 0 .. NB*(SQ-1)-1
    int b = blk / (SQ - 1);
    int s = 1 + (blk % (SQ - 1));       // skip row 0 (never used by the reference)
    const float4* row =
        (const float4*)(batch + (size_t)(b * SQ + s) * ROWW);
    int t = threadIdx.x;                // 0..255

    int local = -1;                     // position of nonzero within row (at most one)
    #pragma unroll
    for (int c = 0; c < 8; ++c) {
        float4 v = row[c * 256 + t];    // 2048 float4 per row
        int base = (c * 256 + t) * 4;
        if (v.x != 0.0f) local = base + 0;
        if (v.y != 0.0f) local = base + 1;
        if (v.z != 0.0f) local = base + 2;
        if (v.w != 0.0f) local = base + 3;
    }

    // block max-reduce (at most one thread holds a value >= 0)
    #pragma unroll
    for (int off = 16; off; off >>= 1)
        local = max(local, __shfl_xor_sync(0xffffffffu, local, off));
    __shared__ int smax[8];
    if ((t & 31) == 0) smax[t >> 5] = local;
    __syncthreads();
    if (t == 0) {
        int m = smax[0];
        #pragma unroll
        for (int w = 1; w < 8; ++w) m = max(m, smax[w]);
        int code = -1;
        if (m >= 0) {
            int a = (m < NQ) ? 1 : 0;   // first half = answered correctly
            code = (a << 12) | (m & (NQ - 1));
        }
        g_code[b * SQ + s] = code;
    }
}

// ---------------------------------------------------------------------------
// Phase 2: one block per student. Gather pred, BCE, trim index, per-b loss.
// ---------------------------------------------------------------------------
__global__ __launch_bounds__(256) void per_batch(const float* __restrict__ pred,
                                                 const float* __restrict__ target_q,
                                                 const float* __restrict__ target_label) {
    int b = blockIdx.x;
    int t = threadIdx.x;                 // s index for t < SQ-1

    float bce = 0.0f;
    int   idx = 1 << 20;                 // sentinel for min-reduce
    if (t < SQ - 1) {
        int code = g_code[b * SQ + t + 1];
        if (code >= 0) {
            float p = pred[(size_t)(b * SQ + t) * NQ + (code & (NQ - 1))];
            float a = (float)((code >> 12) & 1);
            float lp  = fmaxf(logf(p),    -100.0f);
            float l1p = fmaxf(log1pf(-p), -100.0f);
            bce = -(a * lp + (1.0f - a) * l1p);
            idx = t;                     // p > 0 guaranteed (pred in (0.01,0.99))
        }
        // padded (code<0): p=0, a=0  ->  BCE == 0, contributes nothing (matches ref)
    }

    // block reduce: sum(bce), min(idx) — fixed tree, deterministic
    #pragma unroll
    for (int off = 16; off; off >>= 1) {
        bce += __shfl_xor_sync(0xffffffffu, bce, off);
        idx  = min(idx, __shfl_xor_sync(0xffffffffu, idx, off));
    }
    __shared__ float ssum[8];
    __shared__ int   smin[8];
    if ((t & 31) == 0) { ssum[t >> 5] = bce; smin[t >> 5] = idx; }
    __syncthreads();
    if (t == 0) {
        float total = ssum[0];
        int   im    = smin[0];
        #pragma unroll
        for (int w = 1; w < 8; ++w) { total += ssum[w]; im = min(im, smin[w]); }
        if (im >= SQ - 1) im = 0;        // argmax of all-False returns 0 (ref semantics)

        float p = target_q[b];           // target_q is [B,1]
        float a = target_label[b];
        float tail = -(a * fmaxf(logf(p), -100.0f) +
                       (1.0f - a) * fmaxf(log1pf(-p), -100.0f));
        float n = (float)(SQ - im);      // (S-1) - i + 1
        g_partial[b] = (total + tail) / n;
    }
}

// ---------------------------------------------------------------------------
// Phase 3: fold 64 partials into the scalar output.
// ---------------------------------------------------------------------------
__global__ void final_sum(float* __restrict__ out) {
    int t = threadIdx.x;                 // 32 threads
    float v = g_partial[t] + g_partial[t + 32];
    #pragma unroll
    for (int off = 16; off; off >>= 1)
        v += __shfl_xor_sync(0xffffffffu, v, off);
    if (t == 0) out[0] = v;
}

// ---------------------------------------------------------------------------
extern "C" void kernel_launch(void* const* d_in, const int* in_sizes, int n_in,
                              void* d_out, int out_size) {
    const float *pred = nullptr, *batch = nullptr, *tq = nullptr, *tl = nullptr;
    for (int i = 0; i < n_in; ++i) {
        long sz = in_sizes[i];
        if (sz == (long)NB * SQ * NQ)          pred  = (const float*)d_in[i];
        else if (sz == (long)NB * SQ * ROWW)   batch = (const float*)d_in[i];
        else if (sz == NB) {                    // dict order: target_q then target_label
            if (!tq) tq = (const float*)d_in[i];
            else     tl = (const float*)d_in[i];
        }
    }

    scan_rows<<<NB * (SQ - 1), 256>>>(batch);
    per_batch<<<NB, 256>>>(pred, tq, tl);
    final_sum<<<1, 32>>>((float*)d_out);
}

// round 5
// speedup vs baseline: 1.3469x; 1.3469x over previous
#include <cuda_runtime.h>
#include <math.h>

// Problem constants (match reference)
#define NQ   4096     // NUM_Q
#define SQ   256      // MAX_STEP
#define NB   64       // BATCH
#define ROWW (2 * NQ) // 8192 floats per batch row

// Scratch (no device allocation allowed)
__device__ int   g_code[NB * SQ];   // per (b,s): (a<<12)|q_idx, or -1 if padded row
__device__ float g_partial[NB];     // per-student loss

// ---------------------------------------------------------------------------
// Phase 1: scan batch rows s=1..255 for the single one-hot position.
// One block (256 threads) per row. Sequential 4KB chunks (1 float4/thread)
// with block-wide early exit: expected 4.1 of 8 chunks read (q uniform in
// [0,4096), first half with p=0.6), cutting DRAM traffic to ~53%.
// ---------------------------------------------------------------------------
__global__ __launch_bounds__(256) void scan_rows(const float* __restrict__ batch) {
    int blk = blockIdx.x;               // 0 .. NB*(SQ-1)-1
    int b = blk / (SQ - 1);
    int s = 1 + (blk % (SQ - 1));       // row 0 is never used by the reference
    const float4* row =
        (const float4*)(batch + (size_t)(b * SQ + s) * ROWW);
    int t = threadIdx.x;                // 0..255

    int local = -1;                     // position of nonzero within row
    #pragma unroll 1
    for (int c = 0; c < 8; ++c) {
        float4 v = row[c * 256 + t];    // contiguous 4KB chunk per step
        int base = (c * 256 + t) * 4;
        if (v.x != 0.0f) local = base + 0;
        if (v.y != 0.0f) local = base + 1;
        if (v.z != 0.0f) local = base + 2;
        if (v.w != 0.0f) local = base + 3;
        // uniform block-wide decision -> safe to break
        if (__syncthreads_or(local >= 0)) break;
    }

    // block max-reduce (at most one thread holds a value >= 0)
    #pragma unroll
    for (int off = 16; off; off >>= 1)
        local = max(local, __shfl_xor_sync(0xffffffffu, local, off));
    __shared__ int smax[8];
    if ((t & 31) == 0) smax[t >> 5] = local;
    __syncthreads();
    if (t == 0) {
        int m = smax[0];
        #pragma unroll
        for (int w = 1; w < 8; ++w) m = max(m, smax[w]);
        int code = -1;
        if (m >= 0) {
            int a = (m < NQ) ? 1 : 0;   // first half = answered correctly
            code = (a << 12) | (m & (NQ - 1));
        }
        g_code[b * SQ + s] = code;
    }
}

// ---------------------------------------------------------------------------
// Phase 2: one block per student. Gather pred, BCE, trim index, per-b loss.
// ---------------------------------------------------------------------------
__global__ __launch_bounds__(256) void per_batch(const float* __restrict__ pred,
                                                 const float* __restrict__ target_q,
                                                 const float* __restrict__ target_label) {
    int b = blockIdx.x;
    int t = threadIdx.x;                 // s index for t < SQ-1

    float bce = 0.0f;
    int   idx = 1 << 20;                 // sentinel for min-reduce
    if (t < SQ - 1) {
        int code = g_code[b * SQ + t + 1];
        if (code >= 0) {
            float p = pred[(size_t)(b * SQ + t) * NQ + (code & (NQ - 1))];
            float a = (float)((code >> 12) & 1);
            float lp  = fmaxf(logf(p),    -100.0f);
            float l1p = fmaxf(log1pf(-p), -100.0f);
            bce = -(a * lp + (1.0f - a) * l1p);
            idx = t;                     // p > 0 guaranteed (pred in (0.01,0.99))
        }
        // padded (code<0): p=0, a=0  ->  BCE == 0, contributes nothing (matches ref)
    }

    // block reduce: sum(bce), min(idx) — fixed tree, deterministic
    #pragma unroll
    for (int off = 16; off; off >>= 1) {
        bce += __shfl_xor_sync(0xffffffffu, bce, off);
        idx  = min(idx, __shfl_xor_sync(0xffffffffu, idx, off));
    }
    __shared__ float ssum[8];
    __shared__ int   smin[8];
    if ((t & 31) == 0) { ssum[t >> 5] = bce; smin[t >> 5] = idx; }
    __syncthreads();
    if (t == 0) {
        float total = ssum[0];
        int   im    = smin[0];
        #pragma unroll
        for (int w = 1; w < 8; ++w) { total += ssum[w]; im = min(im, smin[w]); }
        if (im >= SQ - 1) im = 0;        // argmax of all-False returns 0 (ref semantics)

        float p = target_q[b];           // target_q is [B,1]
        float a = target_label[b];
        float tail = -(a * fmaxf(logf(p), -100.0f) +
                       (1.0f - a) * fmaxf(log1pf(-p), -100.0f));
        float n = (float)(SQ - im);      // (S-1) - i + 1
        g_partial[b] = (total + tail) / n;
    }
}

// ---------------------------------------------------------------------------
// Phase 3: fold 64 partials into the scalar output.
// ---------------------------------------------------------------------------
__global__ void final_sum(float* __restrict__ out) {
    int t = threadIdx.x;                 // 32 threads
    float v = g_partial[t] + g_partial[t + 32];
    #pragma unroll
    for (int off = 16; off; off >>= 1)
        v += __shfl_xor_sync(0xffffffffu, v, off);
    if (t == 0) out[0] = v;
}

// ---------------------------------------------------------------------------
extern "C" void kernel_launch(void* const* d_in, const int* in_sizes, int n_in,
                              void* d_out, int out_size) {
    const float *pred = nullptr, *batch = nullptr, *tq = nullptr, *tl = nullptr;
    for (int i = 0; i < n_in; ++i) {
        long sz = in_sizes[i];
        if (sz == (long)NB * SQ * NQ)          pred  = (const float*)d_in[i];
        else if (sz == (long)NB * SQ * ROWW)   batch = (const float*)d_in[i];
        else if (sz == NB) {                    // dict order: target_q then target_label
            if (!tq) tq = (const float*)d_in[i];
            else     tl = (const float*)d_in[i];
        }
    }

    scan_rows<<<NB * (SQ - 1), 256>>>(batch);
    per_batch<<<NB, 256>>>(pred, tq, tl);
    final_sum<<<1, 32>>>((float*)d_out);
}

// round 7
// speedup vs baseline: 1.5331x; 1.1382x over previous
#include <cuda_runtime.h>
#include <math.h>

// Problem constants (match reference)
#define NQ   4096     // NUM_Q
#define SQ   256      // MAX_STEP
#define NB   64       // BATCH
#define ROWW (2 * NQ) // 8192 floats per batch row
#define NROWS (NB * (SQ - 1))   // 16320 scanned rows (s=1..255)

// Scratch (no device allocation allowed)
__device__ int   g_code[NB * SQ];   // per (b,s): (a<<12)|q_idx, or -1 if padded row
__device__ float g_partial[NB];     // per-student loss

// ---------------------------------------------------------------------------
// Phase 1: warp-per-row scan for the single one-hot position.
// Each warp streams its row in 2KB super-chunks (4 coalesced 512B segments,
// MLP=4), early-exiting via __ballot_sync (no block barriers). Expected
// 7.7/16 chunks read => ~15.4KB per 32KB row => ~251MB total DRAM traffic.
// ---------------------------------------------------------------------------
__global__ __launch_bounds__(256) void scan_rows(const float* __restrict__ batch) {
    int w    = threadIdx.x >> 5;        // warp in block: 0..7
    int lane = threadIdx.x & 31;
    int r    = blockIdx.x * 8 + w;      // row id 0..NROWS-1
    int b = r / (SQ - 1);
    int s = 1 + (r % (SQ - 1));         // row 0 is never used by the reference
    const float4* row =
        (const float4*)(batch + (size_t)(b * SQ + s) * ROWW);

    int local = -1;                     // float position of nonzero (if in my lanes)
    #pragma unroll 1
    for (int c = 0; c < 16; ++c) {      // 16 x 2KB super-chunks per row
        // 4 independent 512B segments -> 4 outstanding loads per lane
        float4 v0 = row[c * 128 +   0 + lane];
        float4 v1 = row[c * 128 +  32 + lane];
        float4 v2 = row[c * 128 +  64 + lane];
        float4 v3 = row[c * 128 +  96 + lane];

        int b0 = (c * 128 +   0 + lane) * 4;
        int b1 = (c * 128 +  32 + lane) * 4;
        int b2 = (c * 128 +  64 + lane) * 4;
        int b3 = (c * 128 +  96 + lane) * 4;
        if (v0.x != 0.0f) local = b0 + 0;
        if (v0.y != 0.0f) local = b0 + 1;
        if (v0.z != 0.0f) local = b0 + 2;
        if (v0.w != 0.0f) local = b0 + 3;
        if (v1.x != 0.0f) local = b1 + 0;
        if (v1.y != 0.0f) local = b1 + 1;
        if (v1.z != 0.0f) local = b1 + 2;
        if (v1.w != 0.0f) local = b1 + 3;
        if (v2.x != 0.0f) local = b2 + 0;
        if (v2.y != 0.0f) local = b2 + 1;
        if (v2.z != 0.0f) local = b2 + 2;
        if (v2.w != 0.0f) local = b2 + 3;
        if (v3.x != 0.0f) local = b3 + 0;
        if (v3.y != 0.0f) local = b3 + 1;
        if (v3.z != 0.0f) local = b3 + 2;
        if (v3.w != 0.0f) local = b3 + 3;

        if (__ballot_sync(0xffffffffu, local >= 0)) break;  // warp-uniform exit
    }

    // warp max-reduce: at most one lane holds a value >= 0
    #pragma unroll
    for (int off = 16; off; off >>= 1)
        local = max(local, __shfl_xor_sync(0xffffffffu, local, off));

    if (lane == 0) {
        int code = -1;
        if (local >= 0) {
            int a = (local < NQ) ? 1 : 0;   // first half = answered correctly
            code = (a << 12) | (local & (NQ - 1));
        }
        g_code[b * SQ + s] = code;
    }
}

// ---------------------------------------------------------------------------
// Phase 2: one block per student. Gather pred, BCE, trim index, per-b loss.
// ---------------------------------------------------------------------------
__global__ __launch_bounds__(256) void per_batch(const float* __restrict__ pred,
                                                 const float* __restrict__ target_q,
                                                 const float* __restrict__ target_label) {
    int b = blockIdx.x;
    int t = threadIdx.x;                 // s index for t < SQ-1

    float bce = 0.0f;
    int   idx = 1 << 20;                 // sentinel for min-reduce
    if (t < SQ - 1) {
        int code = g_code[b * SQ + t + 1];
        if (code >= 0) {
            float p = pred[(size_t)(b * SQ + t) * NQ + (code & (NQ - 1))];
            float a = (float)((code >> 12) & 1);
            float lp  = fmaxf(logf(p),    -100.0f);
            float l1p = fmaxf(log1pf(-p), -100.0f);
            bce = -(a * lp + (1.0f - a) * l1p);
            idx = t;                     // p > 0 guaranteed (pred in (0.01,0.99))
        }
        // padded (code<0): p=0, a=0  ->  BCE == 0, contributes nothing (matches ref)
    }

    // block reduce: sum(bce), min(idx) — fixed tree, deterministic
    #pragma unroll
    for (int off = 16; off; off >>= 1) {
        bce += __shfl_xor_sync(0xffffffffu, bce, off);
        idx  = min(idx, __shfl_xor_sync(0xffffffffu, idx, off));
    }
    __shared__ float ssum[8];
    __shared__ int   smin[8];
    if ((t & 31) == 0) { ssum[t >> 5] = bce; smin[t >> 5] = idx; }
    __syncthreads();
    if (t == 0) {
        float total = ssum[0];
        int   im    = smin[0];
        #pragma unroll
        for (int w = 1; w < 8; ++w) { total += ssum[w]; im = min(im, smin[w]); }
        if (im >= SQ - 1) im = 0;        // argmax of all-False returns 0 (ref semantics)

        float p = target_q[b];           // target_q is [B,1]
        float a = target_label[b];
        float tail = -(a * fmaxf(logf(p), -100.0f) +
                       (1.0f - a) * fmaxf(log1pf(-p), -100.0f));
        float n = (float)(SQ - im);      // (S-1) - i + 1
        g_partial[b] = (total + tail) / n;
    }
}

// ---------------------------------------------------------------------------
// Phase 3: fold 64 partials into the scalar output.
// ---------------------------------------------------------------------------
__global__ void final_sum(float* __restrict__ out) {
    int t = threadIdx.x;                 // 32 threads
    float v = g_partial[t] + g_partial[t + 32];
    #pragma unroll
    for (int off = 16; off; off >>= 1)
        v += __shfl_xor_sync(0xffffffffu, v, off);
    if (t == 0) out[0] = v;
}

// ---------------------------------------------------------------------------
extern "C" void kernel_launch(void* const* d_in, const int* in_sizes, int n_in,
                              void* d_out, int out_size) {
    const float *pred = nullptr, *batch = nullptr, *tq = nullptr, *tl = nullptr;
    for (int i = 0; i < n_in; ++i) {
        long sz = in_sizes[i];
        if (sz == (long)NB * SQ * NQ)          pred  = (const float*)d_in[i];
        else if (sz == (long)NB * SQ * ROWW)   batch = (const float*)d_in[i];
        else if (sz == NB) {                    // dict order: target_q then target_label
            if (!tq) tq = (const float*)d_in[i];
            else     tl = (const float*)d_in[i];
        }
    }

    scan_rows<<<NROWS / 8, 256>>>(batch);
    per_batch<<<NB, 256>>>(pred, tq, tl);
    final_sum<<<1, 32>>>((float*)d_out);
}